// round 1
// baseline (speedup 1.0000x reference)
#include <cuda_runtime.h>

// ---------------------------------------------------------------------------
// ImplicitMeshDecoder: fused coordinate-MLP
//   rows M = B*P = 2 * 64^3 = 524288, hidden H = 512
//   layer0: silu(latb0[b] + x*Wc0 + y*Wc1 + z*Wc2)   (analytic coords)
//   layer1: silu(h @ W1 + b1)   512x512 GEMM
//   layer2: silu(h @ W2 + b2)   512x512 GEMM
//   layer3: h @ W3 + b3         512->1
// Strategy: one CTA per 64-row tile; activations live in SMEM (128 KB);
// weights streamed in 8-row k-tiles (double-buffered, 32 KB); 8x8 register
// blocking per thread with packed fma.rn.f32x2 (Blackwell 2x fp32 rate).
// ---------------------------------------------------------------------------

#define HDIM     512
#define MTILE    64
#define NTHREADS 512
#define KT       8
#define PGRID    262144    // 64^3
#define BATCH    2
#define NBLOCKS  ((BATCH * PGRID) / MTILE)   // 8192

__device__ float g_latb0[BATCH * HDIM];

// ---- packed f32x2 helpers --------------------------------------------------
__device__ __forceinline__ void fma2(unsigned long long& d,
                                     unsigned long long a,
                                     unsigned long long b) {
    asm("fma.rn.f32x2 %0, %1, %2, %0;" : "+l"(d) : "l"(a), "l"(b));
}
__device__ __forceinline__ unsigned long long pack2(float v) {
    unsigned long long r;
    asm("mov.b64 %0, {%1, %1};" : "=l"(r) : "f"(v));
    return r;
}
__device__ __forceinline__ void unpack2(unsigned long long v, float& lo, float& hi) {
    asm("mov.b64 {%0, %1}, %2;" : "=f"(lo), "=f"(hi) : "l"(v));
}

__device__ __forceinline__ float silu(float v) {
    // v / (1 + e^-v); MUFU-based, ~1e-6 rel err, saturates correctly at +/-inf
    return __fdividef(v, 1.0f + __expf(-v));
}

// ---- pre-kernel: latb0[b][h] = cad_latent[b] @ W0[:512] + b0 ---------------
__global__ void latb0_kernel(const float* __restrict__ lat,
                             const float* __restrict__ W0,
                             const float* __restrict__ b0) {
    int b = blockIdx.x;          // 2 blocks
    int h = threadIdx.x;         // 512 threads
    const float* L = lat + b * HDIM;
    float acc = b0[h];
#pragma unroll 8
    for (int d = 0; d < HDIM; d++)
        acc = fmaf(L[d], W0[d * HDIM + h], acc);
    g_latb0[b * HDIM + h] = acc;
}

// ---- main fused kernel -----------------------------------------------------
__global__ __launch_bounds__(NTHREADS, 1)
void mlp_fused_kernel(const float* __restrict__ W0,   // (515, 512)
                      const float* __restrict__ W1,
                      const float* __restrict__ b1,
                      const float* __restrict__ W2,
                      const float* __restrict__ b2,
                      const float* __restrict__ W3,   // (512, 1)
                      const float* __restrict__ b3,
                      float* __restrict__ out) {
    extern __shared__ float smem[];
    float* sh = smem;                        // MTILE * HDIM activations
    float* sw = smem + MTILE * HDIM;         // 2 * KT * HDIM weight stage

    const int tid = threadIdx.x;
    const int tx  = tid & 63;    // column group: cols n = tx*2 + 128*jp (+0/1)
    const int ty  = tid >> 6;    // row group:    rows m = ty*8 + i
    const int m0  = blockIdx.x * MTILE;

    // ---------------- layer 0: analytic coords + latent ----------------
    {
        const float* Wc = W0 + (size_t)HDIM * HDIM;   // rows 512..514 of W0
        const int b = m0 >> 18;                       // P = 2^18; tile never crosses batch
        // hoist per-column weight/latent loads (shared by the 8 rows)
        float latv[8], c0[8], c1[8], c2[8];
#pragma unroll
        for (int jp = 0; jp < 4; jp++) {
#pragma unroll
            for (int c = 0; c < 2; c++) {
                int n = tx * 2 + 128 * jp + c;
                latv[jp * 2 + c] = g_latb0[b * HDIM + n];
                c0[jp * 2 + c]   = Wc[n];
                c1[jp * 2 + c]   = Wc[HDIM + n];
                c2[jp * 2 + c]   = Wc[2 * HDIM + n];
            }
        }
#pragma unroll
        for (int i = 0; i < 8; i++) {
            int mg = m0 + ty * 8 + i;
            int p  = mg & (PGRID - 1);
            float x = -1.2f + (float)(p >> 12)        * (2.4f / 63.0f);
            float y = -1.2f + (float)((p >> 6) & 63)  * (2.4f / 63.0f);
            float z = -1.2f + (float)(p & 63)         * (2.4f / 63.0f);
            float* row = sh + (ty * 8 + i) * HDIM;
#pragma unroll
            for (int q = 0; q < 8; q++) {
                int n = tx * 2 + 128 * (q >> 1) + (q & 1);
                float pre = latv[q];
                pre = fmaf(x, c0[q], pre);
                pre = fmaf(y, c1[q], pre);
                pre = fmaf(z, c2[q], pre);
                row[n] = silu(pre);
            }
        }
    }
    __syncthreads();

    // ---------------- layers 1 & 2: 512x512 GEMM + silu ----------------
    const float* Ws[2] = {W1, W2};
    const float* Bs[2] = {b1, b2};

    for (int layer = 0; layer < 2; layer++) {
        const float*  W  = Ws[layer];
        const float*  bv = Bs[layer];
        const float4* W4 = (const float4*)W;

        unsigned long long acc[8][4];
#pragma unroll
        for (int i = 0; i < 8; i++)
#pragma unroll
            for (int jp = 0; jp < 4; jp++) acc[i][jp] = 0ull;

        // prologue: stage k-tile 0
        float4 r0 = __ldg(W4 + 0 * (KT * HDIM / 4) + tid);
        float4 r1 = __ldg(W4 + 0 * (KT * HDIM / 4) + (NTHREADS) + tid);
        ((float4*)sw)[tid]            = r0;
        ((float4*)sw)[NTHREADS + tid] = r1;
        __syncthreads();

        for (int t = 0; t < HDIM / KT; t++) {
            // prefetch next tile into registers (latency hidden by FFMA body)
            if (t < HDIM / KT - 1) {
                r0 = __ldg(W4 + (t + 1) * (KT * HDIM / 4) + tid);
                r1 = __ldg(W4 + (t + 1) * (KT * HDIM / 4) + NTHREADS + tid);
            }
            const float* wbase = sw + (t & 1) * (KT * HDIM);
            const float* hbase = sh + (ty * 8) * HDIM + t * KT;

#pragma unroll
            for (int kp = 0; kp < KT / 2; kp++) {
                float2 hv[8];
#pragma unroll
                for (int i = 0; i < 8; i++)  // broadcast LDS.64 within warp
                    hv[i] = *(const float2*)(hbase + i * HDIM + kp * 2);
#pragma unroll
                for (int kk = 0; kk < 2; kk++) {
                    unsigned long long w2[4];
#pragma unroll
                    for (int jp = 0; jp < 4; jp++)
                        w2[jp] = *(const unsigned long long*)
                                 (wbase + (kp * 2 + kk) * HDIM + tx * 2 + 128 * jp);
#pragma unroll
                    for (int i = 0; i < 8; i++) {
                        unsigned long long h2 = pack2(kk ? hv[i].y : hv[i].x);
#pragma unroll
                        for (int jp = 0; jp < 4; jp++)
                            fma2(acc[i][jp], h2, w2[jp]);
                    }
                }
            }

            if (t < HDIM / KT - 1) {
                float* dst = sw + ((t + 1) & 1) * (KT * HDIM);
                ((float4*)dst)[tid]            = r0;
                ((float4*)dst)[NTHREADS + tid] = r1;
            }
            __syncthreads();
        }

        // epilogue: bias + silu, write back to sh (safe: final sync above
        // guarantees every thread finished reading sh)
#pragma unroll
        for (int jp = 0; jp < 4; jp++) {
            int n0 = tx * 2 + 128 * jp;
            float2 bb = *(const float2*)(bv + n0);
#pragma unroll
            for (int i = 0; i < 8; i++) {
                float s0, s1;
                unpack2(acc[i][jp], s0, s1);
                s0 = silu(s0 + bb.x);
                s1 = silu(s1 + bb.y);
                *(float2*)(sh + (ty * 8 + i) * HDIM + n0) = make_float2(s0, s1);
            }
        }
        __syncthreads();
    }

    // ---------------- layer 3: 512 -> 1 dot ----------------
    {
        int r8  = tid & 7;        // 8 lanes cooperate per row
        int row = tid >> 3;       // 64 rows
        const float* hrow = sh + row * HDIM;
        float s = 0.0f;
#pragma unroll 8
        for (int c = 0; c < 64; c++) {
            int n = r8 + 8 * c;   // stride-8 to spread banks (<=4-way)
            s = fmaf(hrow[n], W3[n], s);
        }
        s += __shfl_down_sync(0xffffffffu, s, 4, 8);
        s += __shfl_down_sync(0xffffffffu, s, 2, 8);
        s += __shfl_down_sync(0xffffffffu, s, 1, 8);
        if (r8 == 0) out[m0 + row] = s + b3[0];
    }
}

// ---------------------------------------------------------------------------
extern "C" void kernel_launch(void* const* d_in, const int* in_sizes, int n_in,
                              void* d_out, int out_size) {
    const float* lat = (const float*)d_in[0];
    const float* W0  = (const float*)d_in[1];
    const float* b0  = (const float*)d_in[2];
    const float* W1  = (const float*)d_in[3];
    const float* b1  = (const float*)d_in[4];
    const float* W2  = (const float*)d_in[5];
    const float* b2  = (const float*)d_in[6];
    const float* W3  = (const float*)d_in[7];
    const float* b3  = (const float*)d_in[8];
    float* out = (float*)d_out;

    latb0_kernel<<<BATCH, HDIM>>>(lat, W0, b0);

    size_t smem = (size_t)(MTILE * HDIM + 2 * KT * HDIM) * sizeof(float); // 160 KB
    cudaFuncSetAttribute(mlp_fused_kernel,
                         cudaFuncAttributeMaxDynamicSharedMemorySize, (int)smem);
    mlp_fused_kernel<<<NBLOCKS, NTHREADS, smem>>>(W0, W1, b1, W2, b2, W3, b3, out);
}